// round 6
// baseline (speedup 1.0000x reference)
#include <cuda_runtime.h>
#include <math.h>

// Problem constants
#define BB 4
#define TT 1024
#define HH 1024
#define NHEAD 16
#define HDIM 64
#define ROWS (BB*TT)          // 4096

// ---------------- scratch (no allocs allowed) ----------------
__device__ float g_h [ROWS*HH];        // h (LN1 out), reused as h2 (LN2 out)
__device__ float g_q [ROWS*HH];        // [b][head][t][d]
__device__ float g_k [ROWS*HH];
__device__ float g_v [ROWS*HH];
__device__ float g_x1[ROWS*HH];        // x + attn out
__device__ float g_m1[ROWS*4*HH];      // gelu(h2@W1+b1)  (4096 x 4096)

// ---------------- LayerNorm: one block per row ----------------
__global__ __launch_bounds__(256) void ln_kernel(
    const float* __restrict__ x, const float* __restrict__ g,
    const float* __restrict__ b, float* __restrict__ out)
{
    __shared__ float red[8];
    const int row = blockIdx.x, tid = threadIdx.x;
    const float* xr = x + (size_t)row * HH;
    float4 v = *(const float4*)(xr + tid * 4);

    float s = v.x + v.y + v.z + v.w;
    #pragma unroll
    for (int o = 16; o > 0; o >>= 1) s += __shfl_xor_sync(0xffffffffu, s, o);
    if ((tid & 31) == 0) red[tid >> 5] = s;
    __syncthreads();
    float tot = red[0]+red[1]+red[2]+red[3]+red[4]+red[5]+red[6]+red[7];
    const float mu = tot * (1.0f / HH);

    float dx = v.x - mu, dy = v.y - mu, dz = v.z - mu, dw = v.w - mu;
    float ss = dx*dx + dy*dy + dz*dz + dw*dw;
    #pragma unroll
    for (int o = 16; o > 0; o >>= 1) ss += __shfl_xor_sync(0xffffffffu, ss, o);
    __syncthreads();                      // everyone done reading red
    if ((tid & 31) == 0) red[tid >> 5] = ss;
    __syncthreads();
    float tot2 = red[0]+red[1]+red[2]+red[3]+red[4]+red[5]+red[6]+red[7];
    const float rs = rsqrtf(tot2 * (1.0f / HH) + 1e-5f);

    float4 gv = *(const float4*)(g + tid * 4);
    float4 bv = *(const float4*)(b + tid * 4);
    float4 o4;
    o4.x = dx * rs * gv.x + bv.x;
    o4.y = dy * rs * gv.y + bv.y;
    o4.z = dz * rs * gv.z + bv.z;
    o4.w = dw * rs * gv.w + bv.w;
    *(float4*)(out + (size_t)row * HH + tid * 4) = o4;
}

// ---------------- SGEMM 128x128x16, 256 thr, 8x8 per thread ----------------
// C(epilogue) = A[M,Kd] @ B[Kd,N] + bias
// EPI 0: store to q/k/v in [b][head][t][d] layout
// EPI 1: exact GELU
// EPI 2: + residual (row-major), store row-major
enum { EPI_QKV = 0, EPI_GELU = 1, EPI_RES = 2 };

template <int EPI>
__global__ __launch_bounds__(256) void gemm_k(
    const float* __restrict__ A, const float* __restrict__ B,
    const float* __restrict__ bias, const float* __restrict__ resid,
    float* __restrict__ C, int N, int Kd)
{
    __shared__ float As[16][128];
    __shared__ float Bs[16][128];
    const int tid = threadIdx.x;
    const int tx = tid & 15, ty = tid >> 4;          // 16x16 thread grid
    const int bn = blockIdx.x * 128, bm = blockIdx.y * 128;

    const int aRow = tid >> 2;            // 0..63
    const int aCol = (tid & 3) * 4;       // 0,4,8,12
    const int bRow = tid >> 5;            // 0..7
    const int bCol = (tid & 31) * 4;

    const float* Ap = A + (size_t)(bm + aRow) * Kd + aCol;
    const float* Bp = B + (size_t)bRow * N + bn + bCol;

    float acc[8][8];
    #pragma unroll
    for (int i = 0; i < 8; i++)
        #pragma unroll
        for (int j = 0; j < 8; j++) acc[i][j] = 0.f;

    for (int k0 = 0; k0 < Kd; k0 += 16) {
        float4 a0 = *(const float4*)(Ap);
        float4 a1 = *(const float4*)(Ap + (size_t)64 * Kd);
        As[aCol + 0][aRow]      = a0.x; As[aCol + 1][aRow]      = a0.y;
        As[aCol + 2][aRow]      = a0.z; As[aCol + 3][aRow]      = a0.w;
        As[aCol + 0][aRow + 64] = a1.x; As[aCol + 1][aRow + 64] = a1.y;
        As[aCol + 2][aRow + 64] = a1.z; As[aCol + 3][aRow + 64] = a1.w;
        float4 b0 = *(const float4*)(Bp);
        float4 b1 = *(const float4*)(Bp + (size_t)8 * N);
        *(float4*)&Bs[bRow][bCol]     = b0;
        *(float4*)&Bs[bRow + 8][bCol] = b1;
        __syncthreads();

        #pragma unroll
        for (int kk = 0; kk < 16; kk++) {
            float4 aA = *(const float4*)&As[kk][ty * 8];
            float4 aB = *(const float4*)&As[kk][ty * 8 + 4];
            float4 bA = *(const float4*)&Bs[kk][tx * 8];
            float4 bB = *(const float4*)&Bs[kk][tx * 8 + 4];
            float ar[8] = {aA.x, aA.y, aA.z, aA.w, aB.x, aB.y, aB.z, aB.w};
            float br[8] = {bA.x, bA.y, bA.z, bA.w, bB.x, bB.y, bB.z, bB.w};
            #pragma unroll
            for (int i = 0; i < 8; i++)
                #pragma unroll
                for (int j = 0; j < 8; j++)
                    acc[i][j] += ar[i] * br[j];
        }
        __syncthreads();
        Ap += 16;
        Bp += (size_t)16 * N;
    }

    float bvals[8];
    #pragma unroll
    for (int j = 0; j < 8; j++) bvals[j] = __ldg(&bias[bn + tx * 8 + j]);

    #pragma unroll
    for (int i = 0; i < 8; i++) {
        const int row = bm + ty * 8 + i;
        #pragma unroll
        for (int j = 0; j < 8; j++) {
            const int col = bn + tx * 8 + j;
            float vv = acc[i][j] + bvals[j];
            if (EPI == EPI_QKV) {
                // q[b][head][t][d]
                int idx = ((row >> 10) * NHEAD + (col >> 6)) * (TT * HDIM)
                        + (row & (TT - 1)) * HDIM + (col & (HDIM - 1));
                C[idx] = vv;
            } else if (EPI == EPI_GELU) {
                C[(size_t)row * N + col] =
                    0.5f * vv * (1.0f + erff(vv * 0.70710678118654752f));
            } else {
                size_t o = (size_t)row * N + col;
                C[o] = vv + resid[o];
            }
        }
    }
}

// ---------------- Attention with 1e-9 mask fill, fused residual ----------------
// grid = (16 qtiles, 16 heads, 4 batch), 256 threads
#define ST 68                                   // padded smem stride (16B aligned)
#define ATTN_SMEM (size_t)((4 * 64 * ST + 3 * 64) * sizeof(float))

__global__ __launch_bounds__(256) void attn_kernel(
    const float* __restrict__ q, const float* __restrict__ k,
    const float* __restrict__ v, const float* __restrict__ x,
    float* __restrict__ x1)
{
    extern __shared__ float sm[];
    float* Qs = sm;                // 64 x ST
    float* Ks = Qs + 64 * ST;
    float* Vs = Ks + 64 * ST;
    float* Ss = Vs + 64 * ST;      // scores / probs
    float* mrow = Ss + 64 * ST;    // 64
    float* lrow = mrow + 64;       // 64
    float* arow = lrow + 64;       // 64

    const int tid = threadIdx.x;
    const int tx = tid & 15, ty = tid >> 4;
    const int qt = blockIdx.x, head = blockIdx.y, b = blockIdx.z;
    const int qg0 = qt * 64;

    const float* Qg = q + (size_t)((b * NHEAD + head) * TT + qg0) * HDIM;
    const float* Kg = k + (size_t)(b * NHEAD + head) * TT * HDIM;
    const float* Vg = v + (size_t)(b * NHEAD + head) * TT * HDIM;

    // load Q tile
    for (int i = tid; i < 64 * 16; i += 256) {
        int r = i >> 4, c4 = (i & 15) << 2;
        *(float4*)&Qs[r * ST + c4] = *(const float4*)&Qg[r * 64 + c4];
    }
    if (tid < 64) { mrow[tid] = -1e30f; lrow[tid] = 0.f; }

    float acc[4][4];
    #pragma unroll
    for (int i = 0; i < 4; i++)
        #pragma unroll
        for (int j = 0; j < 4; j++) acc[i][j] = 0.f;

    for (int kt = 0; kt < 16; kt++) {
        __syncthreads();  // prior iter done reading Ks/Vs/Ss
        const float* Kt = Kg + (size_t)kt * 64 * 64;
        const float* Vt = Vg + (size_t)kt * 64 * 64;
        for (int i = tid; i < 64 * 16; i += 256) {
            int r = i >> 4, c4 = (i & 15) << 2;
            *(float4*)&Ks[r * ST + c4] = *(const float4*)&Kt[r * 64 + c4];
            *(float4*)&Vs[r * ST + c4] = *(const float4*)&Vt[r * 64 + c4];
        }
        __syncthreads();

        const int kp0 = kt * 64;
        if (kt > qt) {
            // fully masked tile: score is the constant 1e-9 (still in softmax!)
            #pragma unroll
            for (int qi = 0; qi < 4; qi++)
                #pragma unroll
                for (int ki = 0; ki < 4; ki++)
                    Ss[(ty * 4 + qi) * ST + tx * 4 + ki] = 1e-9f;
        } else {
            float sacc[4][4];
            #pragma unroll
            for (int qi = 0; qi < 4; qi++)
                #pragma unroll
                for (int ki = 0; ki < 4; ki++) sacc[qi][ki] = 0.f;
            #pragma unroll 4
            for (int d = 0; d < 64; d += 4) {
                float4 qv[4], kv[4];
                #pragma unroll
                for (int qi = 0; qi < 4; qi++)
                    qv[qi] = *(const float4*)&Qs[(ty * 4 + qi) * ST + d];
                #pragma unroll
                for (int ki = 0; ki < 4; ki++)
                    kv[ki] = *(const float4*)&Ks[(tx * 4 + ki) * ST + d];
                #pragma unroll
                for (int qi = 0; qi < 4; qi++)
                    #pragma unroll
                    for (int ki = 0; ki < 4; ki++) {
                        sacc[qi][ki] += qv[qi].x * kv[ki].x;
                        sacc[qi][ki] += qv[qi].y * kv[ki].y;
                        sacc[qi][ki] += qv[qi].z * kv[ki].z;
                        sacc[qi][ki] += qv[qi].w * kv[ki].w;
                    }
            }
            #pragma unroll
            for (int qi = 0; qi < 4; qi++)
                #pragma unroll
                for (int ki = 0; ki < 4; ki++) {
                    int qq = ty * 4 + qi, kk = tx * 4 + ki;
                    float s = sacc[qi][ki] * 0.125f;            // 1/sqrt(64)
                    if (kp0 + kk > qg0 + qq) s = 1e-9f;         // mask FILL
                    Ss[qq * ST + kk] = s;
                }
        }
        __syncthreads();

        // per-row max update
        if (tid < 64) {
            float mo = mrow[tid], mn = mo;
            const float* srow = &Ss[tid * ST];
            #pragma unroll 8
            for (int p = 0; p < 64; p++) mn = fmaxf(mn, srow[p]);
            arow[tid] = __expf(mo - mn);
            mrow[tid] = mn;
        }
        __syncthreads();

        // exponentiate in place
        #pragma unroll
        for (int qi = 0; qi < 4; qi++) {
            int qq = ty * 4 + qi;
            float mq = mrow[qq];
            #pragma unroll
            for (int ki = 0; ki < 4; ki++) {
                int kk = tx * 4 + ki;
                Ss[qq * ST + kk] = __expf(Ss[qq * ST + kk] - mq);
            }
        }
        __syncthreads();

        // row sums (2 warps) + accumulator update (all threads), disjoint writes
        if (tid < 64) {
            float s = 0.f;
            const float* srow = &Ss[tid * ST];
            #pragma unroll 8
            for (int p = 0; p < 64; p++) s += srow[p];
            lrow[tid] = lrow[tid] * arow[tid] + s;
        }
        float al[4];
        #pragma unroll
        for (int qi = 0; qi < 4; qi++) al[qi] = arow[ty * 4 + qi];
        #pragma unroll
        for (int qi = 0; qi < 4; qi++)
            #pragma unroll
            for (int di = 0; di < 4; di++) acc[qi][di] *= al[qi];
        #pragma unroll 4
        for (int p = 0; p < 64; p += 4) {
            float4 vv0 = *(const float4*)&Vs[(p + 0) * ST + tx * 4];
            float4 vv1 = *(const float4*)&Vs[(p + 1) * ST + tx * 4];
            float4 vv2 = *(const float4*)&Vs[(p + 2) * ST + tx * 4];
            float4 vv3 = *(const float4*)&Vs[(p + 3) * ST + tx * 4];
            #pragma unroll
            for (int qi = 0; qi < 4; qi++) {
                float4 pw = *(const float4*)&Ss[(ty * 4 + qi) * ST + p];
                acc[qi][0] += pw.x * vv0.x + pw.y * vv1.x + pw.z * vv2.x + pw.w * vv3.x;
                acc[qi][1] += pw.x * vv0.y + pw.y * vv1.y + pw.z * vv2.y + pw.w * vv3.y;
                acc[qi][2] += pw.x * vv0.z + pw.y * vv1.z + pw.z * vv2.z + pw.w * vv3.z;
                acc[qi][3] += pw.x * vv0.w + pw.y * vv1.w + pw.z * vv2.w + pw.w * vv3.w;
            }
        }
    }
    __syncthreads();  // lrow final

    // epilogue: x1 = x + y   (y back to [b][t][H] layout)
    #pragma unroll
    for (int qi = 0; qi < 4; qi++) {
        int qq = ty * 4 + qi;
        float inv = 1.0f / lrow[qq];
        size_t base = ((size_t)(b * TT + qg0 + qq)) * HH + head * HDIM + tx * 4;
        #pragma unroll
        for (int di = 0; di < 4; di++)
            x1[base + di] = x[base + di] + acc[qi][di] * inv;
    }
}

// ---------------- launch ----------------
extern "C" void kernel_launch(void* const* d_in, const int* in_sizes, int n_in,
                              void* d_out, int out_size)
{
    (void)in_sizes; (void)n_in; (void)out_size;
    const float* x    = (const float*)d_in[0];
    const float* ln1g = (const float*)d_in[1];
    const float* ln1b = (const float*)d_in[2];
    const float* ln2g = (const float*)d_in[3];
    const float* ln2b = (const float*)d_in[4];
    const float* Wq   = (const float*)d_in[5];
    const float* bq   = (const float*)d_in[6];
    const float* Wk   = (const float*)d_in[7];
    const float* bk   = (const float*)d_in[8];
    const float* Wv   = (const float*)d_in[9];
    const float* bv   = (const float*)d_in[10];
    const float* W1   = (const float*)d_in[11];
    const float* b1   = (const float*)d_in[12];
    const float* W2   = (const float*)d_in[13];
    const float* b2   = (const float*)d_in[14];
    float* out = (float*)d_out;

    float *h, *q, *k, *v, *x1, *m1;
    cudaGetSymbolAddress((void**)&h,  g_h);
    cudaGetSymbolAddress((void**)&q,  g_q);
    cudaGetSymbolAddress((void**)&k,  g_k);
    cudaGetSymbolAddress((void**)&v,  g_v);
    cudaGetSymbolAddress((void**)&x1, g_x1);
    cudaGetSymbolAddress((void**)&m1, g_m1);

    cudaFuncSetAttribute(attn_kernel,
                         cudaFuncAttributeMaxDynamicSharedMemorySize,
                         (int)ATTN_SMEM);

    // LN1
    ln_kernel<<<ROWS, 256>>>(x, ln1g, ln1b, h);
    // QKV projections (head-permuted stores)
    dim3 gqkv(HH / 128, ROWS / 128);
    gemm_k<EPI_QKV><<<gqkv, 256>>>(h, Wq, bq, nullptr, q, HH, HH);
    gemm_k<EPI_QKV><<<gqkv, 256>>>(h, Wk, bk, nullptr, k, HH, HH);
    gemm_k<EPI_QKV><<<gqkv, 256>>>(h, Wv, bv, nullptr, v, HH, HH);
    // attention + residual
    attn_kernel<<<dim3(TT / 64, NHEAD, BB), 256, ATTN_SMEM>>>(q, k, v, x, x1);
    // LN2 (reuse h)
    ln_kernel<<<ROWS, 256>>>(x1, ln2g, ln2b, h);
    // MLP
    gemm_k<EPI_GELU><<<dim3(4 * HH / 128, ROWS / 128), 256>>>(h, W1, b1, nullptr, m1, 4 * HH, HH);
    gemm_k<EPI_RES> <<<dim3(HH / 128, ROWS / 128), 256>>>(m1, W2, b2, x1, out, HH, 4 * HH);
}

// round 7
// speedup vs baseline: 1.0558x; 1.0558x over previous
#include <cuda_runtime.h>
#include <math.h>

// Problem constants
#define BB 4
#define TT 1024
#define HH 1024
#define NHEAD 16
#define HDIM 64
#define ROWS (BB*TT)          // 4096

// ---------------- scratch (no allocs allowed) ----------------
__device__ float g_h [ROWS*HH];        // h (LN1 out), reused as h2 (LN2 out)
__device__ float g_q [ROWS*HH];        // [b][head][t][d]
__device__ float g_k [ROWS*HH];
__device__ float g_v [ROWS*HH];
__device__ float g_x1[ROWS*HH];        // x + attn out
__device__ float g_m1[ROWS*4*HH];      // gelu(h2@W1+b1)  (4096 x 4096)

// ---------------- LayerNorm: one block per row ----------------
__global__ __launch_bounds__(256) void ln_kernel(
    const float* __restrict__ x, const float* __restrict__ g,
    const float* __restrict__ b, float* __restrict__ out)
{
    __shared__ float red[8];
    const int row = blockIdx.x, tid = threadIdx.x;
    const float* xr = x + (size_t)row * HH;
    float4 v = *(const float4*)(xr + tid * 4);

    float s = v.x + v.y + v.z + v.w;
    #pragma unroll
    for (int o = 16; o > 0; o >>= 1) s += __shfl_xor_sync(0xffffffffu, s, o);
    if ((tid & 31) == 0) red[tid >> 5] = s;
    __syncthreads();
    float tot = red[0]+red[1]+red[2]+red[3]+red[4]+red[5]+red[6]+red[7];
    const float mu = tot * (1.0f / HH);

    float dx = v.x - mu, dy = v.y - mu, dz = v.z - mu, dw = v.w - mu;
    float ss = dx*dx + dy*dy + dz*dz + dw*dw;
    #pragma unroll
    for (int o = 16; o > 0; o >>= 1) ss += __shfl_xor_sync(0xffffffffu, ss, o);
    __syncthreads();                      // everyone done reading red
    if ((tid & 31) == 0) red[tid >> 5] = ss;
    __syncthreads();
    float tot2 = red[0]+red[1]+red[2]+red[3]+red[4]+red[5]+red[6]+red[7];
    const float rs = rsqrtf(tot2 * (1.0f / HH) + 1e-5f);

    float4 gv = *(const float4*)(g + tid * 4);
    float4 bv = *(const float4*)(b + tid * 4);
    float4 o4;
    o4.x = dx * rs * gv.x + bv.x;
    o4.y = dy * rs * gv.y + bv.y;
    o4.z = dz * rs * gv.z + bv.z;
    o4.w = dw * rs * gv.w + bv.w;
    *(float4*)(out + (size_t)row * HH + tid * 4) = o4;
}

// ---------------- SGEMM 128x128x16, 256 thr, 8x8 per thread ----------------
// C(epilogue) = A[M,Kd] @ B[Kd,N] + bias
// EPI 0: store to q/k/v in [b][head][t][d] layout
// EPI 1: exact GELU
// EPI 2: + residual (row-major), store row-major
enum { EPI_QKV = 0, EPI_GELU = 1, EPI_RES = 2 };

template <int EPI>
__global__ __launch_bounds__(256) void gemm_k(
    const float* __restrict__ A, const float* __restrict__ B,
    const float* __restrict__ bias, const float* __restrict__ resid,
    float* __restrict__ C, int N, int Kd)
{
    __shared__ float As[16][128];
    __shared__ float Bs[16][128];
    const int tid = threadIdx.x;
    const int tx = tid & 15, ty = tid >> 4;          // 16x16 thread grid
    const int bn = blockIdx.x * 128, bm = blockIdx.y * 128;

    const int aRow = tid >> 2;            // 0..63
    const int aCol = (tid & 3) * 4;       // 0,4,8,12
    const int bRow = tid >> 5;            // 0..7
    const int bCol = (tid & 31) * 4;

    const float* Ap = A + (size_t)(bm + aRow) * Kd + aCol;
    const float* Bp = B + (size_t)bRow * N + bn + bCol;

    float acc[8][8];
    #pragma unroll
    for (int i = 0; i < 8; i++)
        #pragma unroll
        for (int j = 0; j < 8; j++) acc[i][j] = 0.f;

    for (int k0 = 0; k0 < Kd; k0 += 16) {
        float4 a0 = *(const float4*)(Ap);
        float4 a1 = *(const float4*)(Ap + (size_t)64 * Kd);
        As[aCol + 0][aRow]      = a0.x; As[aCol + 1][aRow]      = a0.y;
        As[aCol + 2][aRow]      = a0.z; As[aCol + 3][aRow]      = a0.w;
        As[aCol + 0][aRow + 64] = a1.x; As[aCol + 1][aRow + 64] = a1.y;
        As[aCol + 2][aRow + 64] = a1.z; As[aCol + 3][aRow + 64] = a1.w;
        float4 b0 = *(const float4*)(Bp);
        float4 b1 = *(const float4*)(Bp + (size_t)8 * N);
        *(float4*)&Bs[bRow][bCol]     = b0;
        *(float4*)&Bs[bRow + 8][bCol] = b1;
        __syncthreads();

        #pragma unroll
        for (int kk = 0; kk < 16; kk++) {
            float4 aA = *(const float4*)&As[kk][ty * 8];
            float4 aB = *(const float4*)&As[kk][ty * 8 + 4];
            float4 bA = *(const float4*)&Bs[kk][tx * 8];
            float4 bB = *(const float4*)&Bs[kk][tx * 8 + 4];
            float ar[8] = {aA.x, aA.y, aA.z, aA.w, aB.x, aB.y, aB.z, aB.w};
            float br[8] = {bA.x, bA.y, bA.z, bA.w, bB.x, bB.y, bB.z, bB.w};
            #pragma unroll
            for (int i = 0; i < 8; i++)
                #pragma unroll
                for (int j = 0; j < 8; j++)
                    acc[i][j] += ar[i] * br[j];
        }
        __syncthreads();
        Ap += 16;
        Bp += (size_t)16 * N;
    }

    float bvals[8];
    #pragma unroll
    for (int j = 0; j < 8; j++) bvals[j] = __ldg(&bias[bn + tx * 8 + j]);

    #pragma unroll
    for (int i = 0; i < 8; i++) {
        const int row = bm + ty * 8 + i;
        #pragma unroll
        for (int j = 0; j < 8; j++) {
            const int col = bn + tx * 8 + j;
            float vv = acc[i][j] + bvals[j];
            if (EPI == EPI_QKV) {
                // q[b][head][t][d]
                int idx = ((row >> 10) * NHEAD + (col >> 6)) * (TT * HDIM)
                        + (row & (TT - 1)) * HDIM + (col & (HDIM - 1));
                C[idx] = vv;
            } else if (EPI == EPI_GELU) {
                C[(size_t)row * N + col] =
                    0.5f * vv * (1.0f + erff(vv * 0.70710678118654752f));
            } else {
                size_t o = (size_t)row * N + col;
                C[o] = vv + resid[o];
            }
        }
    }
}

// ---------------- Attention with 1e-9 mask fill, fused residual ----------------
// grid = (16 qtiles, 16 heads, 4 batch), 256 threads
#define ST 68                                   // padded smem stride (16B aligned)
#define ATTN_SMEM (size_t)((4 * 64 * ST + 3 * 64) * sizeof(float))

__global__ __launch_bounds__(256) void attn_kernel(
    const float* __restrict__ q, const float* __restrict__ k,
    const float* __restrict__ v, const float* __restrict__ x,
    float* __restrict__ x1)
{
    extern __shared__ float sm[];
    float* Qs = sm;                // 64 x ST
    float* Ks = Qs + 64 * ST;
    float* Vs = Ks + 64 * ST;
    float* Ss = Vs + 64 * ST;      // scores / probs
    float* mrow = Ss + 64 * ST;    // 64
    float* lrow = mrow + 64;       // 64
    float* arow = lrow + 64;       // 64

    const int tid = threadIdx.x;
    const int tx = tid & 15, ty = tid >> 4;
    const int qt = blockIdx.x, head = blockIdx.y, b = blockIdx.z;
    const int qg0 = qt * 64;

    const float* Qg = q + (size_t)((b * NHEAD + head) * TT + qg0) * HDIM;
    const float* Kg = k + (size_t)(b * NHEAD + head) * TT * HDIM;
    const float* Vg = v + (size_t)(b * NHEAD + head) * TT * HDIM;

    // load Q tile
    for (int i = tid; i < 64 * 16; i += 256) {
        int r = i >> 4, c4 = (i & 15) << 2;
        *(float4*)&Qs[r * ST + c4] = *(const float4*)&Qg[r * 64 + c4];
    }
    if (tid < 64) { mrow[tid] = -1e30f; lrow[tid] = 0.f; }

    float acc[4][4];
    #pragma unroll
    for (int i = 0; i < 4; i++)
        #pragma unroll
        for (int j = 0; j < 4; j++) acc[i][j] = 0.f;

    for (int kt = 0; kt < 16; kt++) {
        __syncthreads();  // prior iter done reading Ks/Vs/Ss
        const float* Kt = Kg + (size_t)kt * 64 * 64;
        const float* Vt = Vg + (size_t)kt * 64 * 64;
        for (int i = tid; i < 64 * 16; i += 256) {
            int r = i >> 4, c4 = (i & 15) << 2;
            *(float4*)&Ks[r * ST + c4] = *(const float4*)&Kt[r * 64 + c4];
            *(float4*)&Vs[r * ST + c4] = *(const float4*)&Vt[r * 64 + c4];
        }
        __syncthreads();

        const int kp0 = kt * 64;
        if (kt > qt) {
            // fully masked tile: score is the constant 1e-9 (still in softmax!)
            #pragma unroll
            for (int qi = 0; qi < 4; qi++)
                #pragma unroll
                for (int ki = 0; ki < 4; ki++)
                    Ss[(ty * 4 + qi) * ST + tx * 4 + ki] = 1e-9f;
        } else {
            float sacc[4][4];
            #pragma unroll
            for (int qi = 0; qi < 4; qi++)
                #pragma unroll
                for (int ki = 0; ki < 4; ki++) sacc[qi][ki] = 0.f;
            #pragma unroll 4
            for (int d = 0; d < 64; d += 4) {
                float4 qv[4], kv[4];
                #pragma unroll
                for (int qi = 0; qi < 4; qi++)
                    qv[qi] = *(const float4*)&Qs[(ty * 4 + qi) * ST + d];
                #pragma unroll
                for (int ki = 0; ki < 4; ki++)
                    kv[ki] = *(const float4*)&Ks[(tx * 4 + ki) * ST + d];
                #pragma unroll
                for (int qi = 0; qi < 4; qi++)
                    #pragma unroll
                    for (int ki = 0; ki < 4; ki++) {
                        sacc[qi][ki] += qv[qi].x * kv[ki].x;
                        sacc[qi][ki] += qv[qi].y * kv[ki].y;
                        sacc[qi][ki] += qv[qi].z * kv[ki].z;
                        sacc[qi][ki] += qv[qi].w * kv[ki].w;
                    }
            }
            #pragma unroll
            for (int qi = 0; qi < 4; qi++)
                #pragma unroll
                for (int ki = 0; ki < 4; ki++) {
                    int qq = ty * 4 + qi, kk = tx * 4 + ki;
                    float s = sacc[qi][ki] * 0.125f;            // 1/sqrt(64)
                    if (kp0 + kk > qg0 + qq) s = 1e-9f;         // mask FILL
                    Ss[qq * ST + kk] = s;
                }
        }
        __syncthreads();

        // per-row max update
        if (tid < 64) {
            float mo = mrow[tid], mn = mo;
            const float* srow = &Ss[tid * ST];
            #pragma unroll 8
            for (int p = 0; p < 64; p++) mn = fmaxf(mn, srow[p]);
            arow[tid] = __expf(mo - mn);
            mrow[tid] = mn;
        }
        __syncthreads();

        // exponentiate in place
        #pragma unroll
        for (int qi = 0; qi < 4; qi++) {
            int qq = ty * 4 + qi;
            float mq = mrow[qq];
            #pragma unroll
            for (int ki = 0; ki < 4; ki++) {
                int kk = tx * 4 + ki;
                Ss[qq * ST + kk] = __expf(Ss[qq * ST + kk] - mq);
            }
        }
        __syncthreads();

        // row sums (2 warps) + accumulator update (all threads), disjoint writes
        if (tid < 64) {
            float s = 0.f;
            const float* srow = &Ss[tid * ST];
            #pragma unroll 8
            for (int p = 0; p < 64; p++) s += srow[p];
            lrow[tid] = lrow[tid] * arow[tid] + s;
        }
        float al[4];
        #pragma unroll
        for (int qi = 0; qi < 4; qi++) al[qi] = arow[ty * 4 + qi];
        #pragma unroll
        for (int qi = 0; qi < 4; qi++)
            #pragma unroll
            for (int di = 0; di < 4; di++) acc[qi][di] *= al[qi];
        #pragma unroll 4
        for (int p = 0; p < 64; p += 4) {
            float4 vv0 = *(const float4*)&Vs[(p + 0) * ST + tx * 4];
            float4 vv1 = *(const float4*)&Vs[(p + 1) * ST + tx * 4];
            float4 vv2 = *(const float4*)&Vs[(p + 2) * ST + tx * 4];
            float4 vv3 = *(const float4*)&Vs[(p + 3) * ST + tx * 4];
            #pragma unroll
            for (int qi = 0; qi < 4; qi++) {
                float4 pw = *(const float4*)&Ss[(ty * 4 + qi) * ST + p];
                acc[qi][0] += pw.x * vv0.x + pw.y * vv1.x + pw.z * vv2.x + pw.w * vv3.x;
                acc[qi][1] += pw.x * vv0.y + pw.y * vv1.y + pw.z * vv2.y + pw.w * vv3.y;
                acc[qi][2] += pw.x * vv0.z + pw.y * vv1.z + pw.z * vv2.z + pw.w * vv3.z;
                acc[qi][3] += pw.x * vv0.w + pw.y * vv1.w + pw.z * vv2.w + pw.w * vv3.w;
            }
        }
    }
    __syncthreads();  // lrow final

    // epilogue: x1 = x + y   (y back to [b][t][H] layout)
    #pragma unroll
    for (int qi = 0; qi < 4; qi++) {
        int qq = ty * 4 + qi;
        float inv = 1.0f / lrow[qq];
        size_t base = ((size_t)(b * TT + qg0 + qq)) * HH + head * HDIM + tx * 4;
        #pragma unroll
        for (int di = 0; di < 4; di++)
            x1[base + di] = x[base + di] + acc[qi][di] * inv;
    }
}

// ---------------- launch ----------------
extern "C" void kernel_launch(void* const* d_in, const int* in_sizes, int n_in,
                              void* d_out, int out_size)
{
    (void)in_sizes; (void)n_in; (void)out_size;
    const float* x    = (const float*)d_in[0];
    const float* ln1g = (const float*)d_in[1];
    const float* ln1b = (const float*)d_in[2];
    const float* ln2g = (const float*)d_in[3];
    const float* ln2b = (const float*)d_in[4];
    const float* Wq   = (const float*)d_in[5];
    const float* bq   = (const float*)d_in[6];
    const float* Wk   = (const float*)d_in[7];
    const float* bk   = (const float*)d_in[8];
    const float* Wv   = (const float*)d_in[9];
    const float* bv   = (const float*)d_in[10];
    const float* W1   = (const float*)d_in[11];
    const float* b1   = (const float*)d_in[12];
    const float* W2   = (const float*)d_in[13];
    const float* b2   = (const float*)d_in[14];
    float* out = (float*)d_out;

    float *h, *q, *k, *v, *x1, *m1;
    cudaGetSymbolAddress((void**)&h,  g_h);
    cudaGetSymbolAddress((void**)&q,  g_q);
    cudaGetSymbolAddress((void**)&k,  g_k);
    cudaGetSymbolAddress((void**)&v,  g_v);
    cudaGetSymbolAddress((void**)&x1, g_x1);
    cudaGetSymbolAddress((void**)&m1, g_m1);

    cudaFuncSetAttribute(attn_kernel,
                         cudaFuncAttributeMaxDynamicSharedMemorySize,
                         (int)ATTN_SMEM);

    // LN1
    ln_kernel<<<ROWS, 256>>>(x, ln1g, ln1b, h);
    // QKV projections (head-permuted stores)
    dim3 gqkv(HH / 128, ROWS / 128);
    gemm_k<EPI_QKV><<<gqkv, 256>>>(h, Wq, bq, nullptr, q, HH, HH);
    gemm_k<EPI_QKV><<<gqkv, 256>>>(h, Wk, bk, nullptr, k, HH, HH);
    gemm_k<EPI_QKV><<<gqkv, 256>>>(h, Wv, bv, nullptr, v, HH, HH);
    // attention + residual
    attn_kernel<<<dim3(TT / 64, NHEAD, BB), 256, ATTN_SMEM>>>(q, k, v, x, x1);
    // LN2 (reuse h)
    ln_kernel<<<ROWS, 256>>>(x1, ln2g, ln2b, h);
    // MLP
    gemm_k<EPI_GELU><<<dim3(4 * HH / 128, ROWS / 128), 256>>>(h, W1, b1, nullptr, m1, 4 * HH, HH);
    gemm_k<EPI_RES> <<<dim3(HH / 128, ROWS / 128), 256>>>(m1, W2, b2, x1, out, HH, 4 * HH);
}